// round 3
// baseline (speedup 1.0000x reference)
#include <cuda_runtime.h>
#include <math.h>

#define BATCH 8
#define CIN   512
#define CK    256
#define CV    256
#define COUT  512
#define NPIX  16384
#define NP    19
#define EPSV  1e-5f

// ---------------- scratch (device globals; no allocations allowed) ----------------
__device__ float g_k1[BATCH * CK * NPIX];     // 134 MB  raw fk_w @ x
__device__ float g_q2[BATCH * CK * NPIX];     // 134 MB  raw fq_w @ x
__device__ float g_L1[BATCH * NP * NPIX];     // 10 MB   stage-1 logits
__device__ float g_sm2[BATCH * NP * NPIX];    // 10 MB   stage-2 softmax
__device__ float g_q1[NP * CK];               // proxy queries  [p][k]
__device__ float g_k2[NP * CK];               // proxy keys     [p][k]
__device__ float g_aK[CK], g_bK[CK];          // folded BN (k1): z = y*a + b
__device__ float g_aQ[CK], g_bQ[CK];          // folded BN (q2)
__device__ float g_rmax[BATCH * NP], g_rinv[BATCH * NP];
__device__ float g_t[BATCH * CIN * NP];       // t[b][c][p] = sum_n x * sim1
__device__ float g_pctx[BATCH * NP * CV];     // proxy context
__device__ float g_wpc[BATCH * NP * COUT];    // W_w @ proxy_ctx

__device__ __forceinline__ float lrelu(float z) { return z > 0.f ? z : 0.01f * z; }

// ---------------- K0: zero the atomically-accumulated t buffer ----------------
__global__ void k0_zero() {
    int i = blockIdx.x * blockDim.x + threadIdx.x;
    if (i < BATCH * CIN * NP) g_t[i] = 0.f;
}

// ---------------- K1: fused projection SGEMM  y = W @ x  (k1 & q2) ----------------
// 128x128x16 tile, 256 threads, 8x8 per thread, fp32.
#define BM 128
#define BN 128
#define BK 16
__global__ __launch_bounds__(256) void k1_proj(
    const float* __restrict__ x,
    const float* __restrict__ fk_w, const float* __restrict__ fk_b,
    const float* __restrict__ fq_w, const float* __restrict__ fq_b)
{
    const int b   = blockIdx.z;
    const int by  = blockIdx.y;                 // 0..3: {0,1}->k1, {2,3}->q2
    const int bxn = blockIdx.x * BN;
    const float* A    = (by < 2) ? fk_w : fq_w;
    const float* bias = (by < 2) ? fk_b : fq_b;
    float*       C    = (by < 2) ? g_k1 : g_q2;
    const int rbase   = (by & 1) * BM;          // row offset within 256
    const float* Bm   = x + (size_t)b * CIN * NPIX;

    __shared__ float As[BK][BM];
    __shared__ float Bs[BK][BN];

    const int tid = threadIdx.x;
    const int tx = tid & 15, ty = tid >> 4;
    float acc[8][8] = {};

    for (int k0 = 0; k0 < CIN; k0 += BK) {
        #pragma unroll
        for (int it = 0; it < 2; ++it) {
            int idx = tid + it * 256;
            int r  = idx >> 2;
            int c4 = (idx & 3) * 4;
            float4 v = *(const float4*)&A[(size_t)(rbase + r) * CIN + k0 + c4];
            As[c4 + 0][r] = v.x; As[c4 + 1][r] = v.y;
            As[c4 + 2][r] = v.z; As[c4 + 3][r] = v.w;
        }
        #pragma unroll
        for (int it = 0; it < 2; ++it) {
            int idx = tid + it * 256;
            int r  = idx >> 5;
            int c4 = (idx & 31) * 4;
            *(float4*)&Bs[r][c4] = *(const float4*)&Bm[(size_t)(k0 + r) * NPIX + bxn + c4];
        }
        __syncthreads();
        #pragma unroll
        for (int k = 0; k < BK; ++k) {
            float a[8], bb[8];
            *(float4*)&a[0]  = *(float4*)&As[k][ty * 8];
            *(float4*)&a[4]  = *(float4*)&As[k][ty * 8 + 4];
            *(float4*)&bb[0] = *(float4*)&Bs[k][tx * 8];
            *(float4*)&bb[4] = *(float4*)&Bs[k][tx * 8 + 4];
            #pragma unroll
            for (int i = 0; i < 8; ++i)
                #pragma unroll
                for (int j = 0; j < 8; ++j)
                    acc[i][j] += a[i] * bb[j];
        }
        __syncthreads();
    }
    #pragma unroll
    for (int i = 0; i < 8; ++i) {
        int r = rbase + ty * 8 + i;             // channel within 256
        float bv = bias[r];
        #pragma unroll
        for (int j = 0; j < 8; ++j) acc[i][j] += bv;
        float* dst = C + ((size_t)b * CK + r) * NPIX + bxn + tx * 8;
        *(float4*)&dst[0] = *(float4*)&acc[i][0];
        *(float4*)&dst[4] = *(float4*)&acc[i][4];
    }
}

// ---------------- K2: BN batch stats over (b, n) per channel ----------------
__global__ void k2_stats(const float* __restrict__ fk_g, const float* __restrict__ fk_be,
                         const float* __restrict__ fq_g, const float* __restrict__ fq_be)
{
    int c = blockIdx.x;                         // 0..511
    const float* src = (c < CK) ? g_k1 : g_q2;
    int ch = c & (CK - 1);
    int tid = threadIdx.x;
    float s = 0.f, s2 = 0.f;
    for (int b = 0; b < BATCH; ++b) {
        const float* p = src + ((size_t)b * CK + ch) * NPIX;
        for (int n = tid; n < NPIX; n += 256) {
            float v = p[n];
            s += v; s2 += v * v;
        }
    }
    __shared__ float sh[256], sh2[256];
    sh[tid] = s; sh2[tid] = s2; __syncthreads();
    for (int o = 128; o; o >>= 1) {
        if (tid < o) { sh[tid] += sh[tid + o]; sh2[tid] += sh2[tid + o]; }
        __syncthreads();
    }
    if (tid == 0) {
        float M = (float)BATCH * NPIX;
        float mean = sh[0] / M;
        float var  = sh2[0] / M - mean * mean;
        float rstd = rsqrtf(var + EPSV);
        float g  = (c < CK) ? fk_g[ch]  : fq_g[ch];
        float be = (c < CK) ? fk_be[ch] : fq_be[ch];
        float a  = g * rstd;
        float bb = be - mean * a;
        if (c < CK) { g_aK[ch] = a; g_bK[ch] = bb; }
        else        { g_aQ[ch] = a; g_bQ[ch] = bb; }
    }
}

// ---------------- K3: proxy projections q1 / k2 (tiny; BN over P=19) ----------------
__global__ void k3_proxy(const float* __restrict__ pf,
                         const float* __restrict__ pq_w, const float* __restrict__ pq_b,
                         const float* __restrict__ pq_g, const float* __restrict__ pq_be,
                         const float* __restrict__ pk_w, const float* __restrict__ pk_b,
                         const float* __restrict__ pk_g, const float* __restrict__ pk_be)
{
    __shared__ float spf[CIN * NP];             // 38.9 KB
    int tid = threadIdx.x;
    for (int i = tid; i < CIN * NP; i += 256) spf[i] = pf[i];
    __syncthreads();
    const float *w, *bi, *g, *be; float* out;
    if (blockIdx.x == 0) { w = pq_w; bi = pq_b; g = pq_g; be = pq_be; out = g_q1; }
    else                 { w = pk_w; bi = pk_b; g = pk_g; be = pk_be; out = g_k2; }
    int k = tid;                                // one output channel per thread
    float acc[NP];
    float bv = bi[k];
    #pragma unroll
    for (int p = 0; p < NP; ++p) acc[p] = bv;
    for (int c = 0; c < CIN; ++c) {
        float wv = w[(size_t)k * CIN + c];
        #pragma unroll
        for (int p = 0; p < NP; ++p) acc[p] += wv * spf[c * NP + p];
    }
    float mean = 0.f;
    #pragma unroll
    for (int p = 0; p < NP; ++p) mean += acc[p];
    mean /= (float)NP;
    float var = 0.f;
    #pragma unroll
    for (int p = 0; p < NP; ++p) { float d = acc[p] - mean; var += d * d; }
    var /= (float)NP;
    float rstd = rsqrtf(var + EPSV);
    float gg = g[k], bb = be[k];
    #pragma unroll
    for (int p = 0; p < NP; ++p) {
        float z = (acc[p] - mean) * rstd * gg + bb;
        out[p * CK + k] = lrelu(z);
    }
}

// ---------------- K4: stage-1 logits  L1[b,p,n] = sum_k q1[p,k] * act(k1) ----------------
__global__ void k4_logits()
{
    __shared__ float q1s[NP * CK];
    __shared__ float aks[CK], bks[CK];
    int tid = threadIdx.x;                      // 128 threads
    for (int i = tid; i < NP * CK; i += 128) q1s[i] = g_q1[i];
    for (int i = tid; i < CK; i += 128) { aks[i] = g_aK[i]; bks[i] = g_bK[i]; }
    __syncthreads();
    int b = blockIdx.y;
    int n = blockIdx.x * 128 + tid;
    const float* kp = g_k1 + (size_t)b * CK * NPIX + n;
    float acc[NP] = {};
    for (int k = 0; k < CK; ++k) {
        float v = kp[(size_t)k * NPIX];
        v = lrelu(v * aks[k] + bks[k]);
        #pragma unroll
        for (int p = 0; p < NP; ++p) acc[p] += q1s[p * CK + k] * v;
    }
    float* Lp = g_L1 + (size_t)b * NP * NPIX + n;
    #pragma unroll
    for (int p = 0; p < NP; ++p) Lp[(size_t)p * NPIX] = acc[p];
}

// ---------------- K5: softmax row stats over N per (b,p) ----------------
__global__ void k5_smstats()
{
    int row = blockIdx.x;                       // 0..151
    const float* L = g_L1 + (size_t)row * NPIX;
    int tid = threadIdx.x;
    float m = -1e30f;
    for (int n = tid; n < NPIX; n += 256) m = fmaxf(m, L[n]);
    __shared__ float sm[256];
    sm[tid] = m; __syncthreads();
    for (int o = 128; o; o >>= 1) { if (tid < o) sm[tid] = fmaxf(sm[tid], sm[tid + o]); __syncthreads(); }
    float mx = sm[0];
    __syncthreads();
    float s = 0.f;
    for (int n = tid; n < NPIX; n += 256) s += expf(L[n] - mx);
    sm[tid] = s; __syncthreads();
    for (int o = 128; o; o >>= 1) { if (tid < o) sm[tid] += sm[tid + o]; __syncthreads(); }
    if (tid == 0) { g_rmax[row] = mx; g_rinv[row] = 1.f / sm[0]; }
}

// ---------------- K6a: t[b,c,p] += sum_n x[b,c,n] * sim1[b,p,n] ----------------
__global__ void k6a_t(const float* __restrict__ x)
{
    const int b  = blockIdx.y;
    const int n0 = blockIdx.x * 512;            // 32 chunks per batch
    __shared__ float xt[CIN * 17];              // 512 x 16 (+pad)
    __shared__ float ws[NP * 16];
    __shared__ float rmx[NP], rin[NP];
    int tid = threadIdx.x;                      // 256
    if (tid < NP) { rmx[tid] = g_rmax[b * NP + tid]; rin[tid] = g_rinv[b * NP + tid]; }
    float acc0[NP] = {}, acc1[NP] = {};
    const float* xb = x + (size_t)b * CIN * NPIX;
    const float* Lb = g_L1 + (size_t)b * NP * NPIX;
    const int c0 = tid, c1 = tid + 256;
    for (int t0 = 0; t0 < 512; t0 += 16) {
        int nb = n0 + t0;
        __syncthreads();
        for (int i = tid; i < CIN * 16; i += 256) {
            int c = i >> 4, nn = i & 15;
            xt[c * 17 + nn] = xb[(size_t)c * NPIX + nb + nn];
        }
        for (int i = tid; i < NP * 16; i += 256) {
            int p = i >> 4, nn = i & 15;
            ws[i] = expf(Lb[(size_t)p * NPIX + nb + nn] - rmx[p]) * rin[p];
        }
        __syncthreads();
        #pragma unroll
        for (int nn = 0; nn < 16; ++nn) {
            float x0 = xt[c0 * 17 + nn], x1 = xt[c1 * 17 + nn];
            #pragma unroll
            for (int p = 0; p < NP; ++p) {
                float w = ws[p * 16 + nn];
                acc0[p] += w * x0;
                acc1[p] += w * x1;
            }
        }
    }
    float* tb = g_t + (size_t)b * CIN * NP;
    #pragma unroll
    for (int p = 0; p < NP; ++p) {
        atomicAdd(&tb[(size_t)c0 * NP + p], acc0[p]);
        atomicAdd(&tb[(size_t)c1 * NP + p], acc1[p]);
    }
}

// ---------------- K6b: proxy_ctx[b,p,v] = fv_b[v] + sum_c fv_w[v,c] * t[b,c,p] ----------------
__global__ void k6b_pctx(const float* __restrict__ fv_w, const float* __restrict__ fv_b)
{
    int p = blockIdx.x, b = blockIdx.y;
    __shared__ float tc[CIN];
    int tid = threadIdx.x;                      // 256
    const float* tb = g_t + (size_t)b * CIN * NP + p;
    for (int i = tid; i < CIN; i += 256) tc[i] = tb[(size_t)i * NP];
    __syncthreads();
    int v = tid;
    float acc = fv_b[v];
    const float* w = fv_w + (size_t)v * CIN;
    for (int c = 0; c < CIN; ++c) acc += w[c] * tc[c];
    g_pctx[((size_t)b * NP + p) * CV + v] = acc;
}

// ---------------- K7pre: wpc[b,p,o] = sum_v W_w[o,v] * proxy_ctx[b,p,v] ----------------
__global__ void k7pre(const float* __restrict__ W_w)
{
    int p = blockIdx.x, b = blockIdx.y;
    __shared__ float pcs[CV];
    int tid = threadIdx.x;                      // 256
    pcs[tid] = g_pctx[((size_t)b * NP + p) * CV + tid];
    __syncthreads();
    for (int o = tid; o < COUT; o += 256) {
        const float* w = W_w + (size_t)o * CV;
        float acc = 0.f;
        for (int v = 0; v < CV; ++v) acc += w[v] * pcs[v];
        g_wpc[((size_t)b * NP + p) * COUT + o] = acc;
    }
}

// ---------------- K7a: stage-2 softmax per pixel (over P=19) ----------------
__global__ void k7a_sm2()
{
    __shared__ float k2s[NP * CK];
    __shared__ float aqs[CK], bqs[CK];
    int tid = threadIdx.x;                      // 128
    for (int i = tid; i < NP * CK; i += 128) k2s[i] = g_k2[i];
    for (int i = tid; i < CK; i += 128) { aqs[i] = g_aQ[i]; bqs[i] = g_bQ[i]; }
    __syncthreads();
    int b = blockIdx.y;
    int n = blockIdx.x * 128 + tid;
    const float* qp = g_q2 + (size_t)b * CK * NPIX + n;
    float lg[NP] = {};
    for (int k = 0; k < CK; ++k) {
        float v = qp[(size_t)k * NPIX];
        v = lrelu(v * aqs[k] + bqs[k]);
        #pragma unroll
        for (int p = 0; p < NP; ++p) lg[p] += k2s[p * CK + k] * v;
    }
    float mx = lg[0];
    #pragma unroll
    for (int p = 1; p < NP; ++p) mx = fmaxf(mx, lg[p]);
    float s = 0.f;
    #pragma unroll
    for (int p = 0; p < NP; ++p) { lg[p] = expf(lg[p] - mx); s += lg[p]; }
    float inv = 1.f / s;
    float* sp = g_sm2 + (size_t)b * NP * NPIX + n;
    #pragma unroll
    for (int p = 0; p < NP; ++p) sp[(size_t)p * NPIX] = lg[p] * inv;
}

// ---------------- K7b: out[b,o,n] = W_b[o] + sum_p sm2[b,n,p] * wpc[b,p,o] ----------------
__global__ void k7b_out(const float* __restrict__ W_b, float* __restrict__ out)
{
    __shared__ float wps[NP * COUT];            // 38.9 KB
    __shared__ float wbs[COUT];
    int tid = threadIdx.x;                      // 128
    int b = blockIdx.y;
    for (int i = tid; i < NP * COUT; i += 128) wps[i] = g_wpc[(size_t)b * NP * COUT + i];
    for (int i = tid; i < COUT; i += 128) wbs[i] = W_b[i];
    __syncthreads();
    int n = blockIdx.x * 128 + tid;
    float sm[NP];
    const float* sp = g_sm2 + (size_t)b * NP * NPIX + n;
    #pragma unroll
    for (int p = 0; p < NP; ++p) sm[p] = sp[(size_t)p * NPIX];
    float* op = out + (size_t)b * COUT * NPIX + n;
    for (int o = 0; o < COUT; ++o) {
        float acc = wbs[o];
        #pragma unroll
        for (int p = 0; p < NP; ++p) acc += sm[p] * wps[p * COUT + o];
        op[(size_t)o * NPIX] = acc;
    }
}

// ---------------- launch ----------------
extern "C" void kernel_launch(void* const* d_in, const int* in_sizes, int n_in,
                              void* d_out, int out_size)
{
    (void)in_sizes; (void)n_in; (void)out_size;
    const float* x     = (const float*)d_in[0];
    const float* pf    = (const float*)d_in[1];
    const float* fk_w  = (const float*)d_in[2];
    const float* fk_b  = (const float*)d_in[3];
    const float* fk_g  = (const float*)d_in[4];
    const float* fk_be = (const float*)d_in[5];
    const float* fq_w  = (const float*)d_in[6];
    const float* fq_b  = (const float*)d_in[7];
    const float* fq_g  = (const float*)d_in[8];
    const float* fq_be = (const float*)d_in[9];
    const float* fv_w  = (const float*)d_in[10];
    const float* fv_b  = (const float*)d_in[11];
    const float* pq_w  = (const float*)d_in[12];
    const float* pq_b  = (const float*)d_in[13];
    const float* pq_g  = (const float*)d_in[14];
    const float* pq_be = (const float*)d_in[15];
    const float* pk_w  = (const float*)d_in[16];
    const float* pk_b  = (const float*)d_in[17];
    const float* pk_g  = (const float*)d_in[18];
    const float* pk_be = (const float*)d_in[19];
    const float* W_w   = (const float*)d_in[20];
    const float* W_b   = (const float*)d_in[21];
    float* out = (float*)d_out;

    k0_zero<<<(BATCH * CIN * NP + 255) / 256, 256>>>();
    k1_proj<<<dim3(NPIX / 128, 4, BATCH), 256>>>(x, fk_w, fk_b, fq_w, fq_b);
    k2_stats<<<2 * CK, 256>>>(fk_g, fk_be, fq_g, fq_be);
    k3_proxy<<<2, 256>>>(pf, pq_w, pq_b, pq_g, pq_be, pk_w, pk_b, pk_g, pk_be);
    k4_logits<<<dim3(NPIX / 128, BATCH), 128>>>();
    k5_smstats<<<BATCH * NP, 256>>>();
    k6a_t<<<dim3(NPIX / 512, BATCH), 256>>>(x);
    k6b_pctx<<<dim3(NP, BATCH), 256>>>(fv_w, fv_b);
    k7pre<<<dim3(NP, BATCH), 256>>>(W_w);
    k7a_sm2<<<dim3(NPIX / 128, BATCH), 128>>>();
    k7b_out<<<dim3(NPIX / 128, BATCH), 128>>>(W_b, out);
}

// round 4
// speedup vs baseline: 1.0018x; 1.0018x over previous
#include <cuda_runtime.h>
#include <math.h>

#define BATCH 8
#define CIN   512
#define CK    256
#define CV    256
#define COUT  512
#define NPIX  16384
#define NP    19
#define EPSV  1e-5f

// ---------------- scratch (device globals; no allocations allowed) ----------------
__device__ float g_k1[BATCH * CK * NPIX];     // 134 MB  raw fk_w @ x
__device__ float g_q2[BATCH * CK * NPIX];     // 134 MB  raw fq_w @ x
__device__ float g_L1[BATCH * NP * NPIX];     // 10 MB   stage-1 logits
__device__ float g_sm2[BATCH * NP * NPIX];    // 10 MB   stage-2 softmax
__device__ float g_q1[NP * CK];               // proxy queries  [p][k]
__device__ float g_k2[NP * CK];               // proxy keys     [p][k]
__device__ float g_aK[CK], g_bK[CK];          // folded BN (k1): z = y*a + b
__device__ float g_aQ[CK], g_bQ[CK];          // folded BN (q2)
__device__ float g_rmax[BATCH * NP], g_rinv[BATCH * NP];
__device__ float g_t[BATCH * CIN * NP];       // t[b][c][p] = sum_n x * sim1
__device__ float g_pctx[BATCH * NP * CV];     // proxy context
__device__ float g_wpc[BATCH * NP * COUT];    // W_w @ proxy_ctx

__device__ __forceinline__ float lrelu(float z) { return z > 0.f ? z : 0.01f * z; }

// ---------------- K0: zero the atomically-accumulated t buffer ----------------
__global__ void k0_zero() {
    int i = blockIdx.x * blockDim.x + threadIdx.x;
    if (i < BATCH * CIN * NP) g_t[i] = 0.f;
}

// ---------------- K1: fused projection SGEMM  y = W @ x  (k1 & q2) ----------------
// 128x128x16 tile, 256 threads, 8x8 per thread, fp32.
#define BM 128
#define BN 128
#define BK 16
__global__ __launch_bounds__(256) void k1_proj(
    const float* __restrict__ x,
    const float* __restrict__ fk_w, const float* __restrict__ fk_b,
    const float* __restrict__ fq_w, const float* __restrict__ fq_b)
{
    const int b   = blockIdx.z;
    const int by  = blockIdx.y;                 // 0..3: {0,1}->k1, {2,3}->q2
    const int bxn = blockIdx.x * BN;
    const float* A    = (by < 2) ? fk_w : fq_w;
    const float* bias = (by < 2) ? fk_b : fq_b;
    float*       C    = (by < 2) ? g_k1 : g_q2;
    const int rbase   = (by & 1) * BM;          // row offset within 256
    const float* Bm   = x + (size_t)b * CIN * NPIX;

    __shared__ float As[BK][BM];
    __shared__ float Bs[BK][BN];

    const int tid = threadIdx.x;
    const int tx = tid & 15, ty = tid >> 4;
    float acc[8][8] = {};

    for (int k0 = 0; k0 < CIN; k0 += BK) {
        #pragma unroll
        for (int it = 0; it < 2; ++it) {
            int idx = tid + it * 256;
            int r  = idx >> 2;
            int c4 = (idx & 3) * 4;
            float4 v = *(const float4*)&A[(size_t)(rbase + r) * CIN + k0 + c4];
            As[c4 + 0][r] = v.x; As[c4 + 1][r] = v.y;
            As[c4 + 2][r] = v.z; As[c4 + 3][r] = v.w;
        }
        #pragma unroll
        for (int it = 0; it < 2; ++it) {
            int idx = tid + it * 256;
            int r  = idx >> 5;
            int c4 = (idx & 31) * 4;
            *(float4*)&Bs[r][c4] = *(const float4*)&Bm[(size_t)(k0 + r) * NPIX + bxn + c4];
        }
        __syncthreads();
        #pragma unroll
        for (int k = 0; k < BK; ++k) {
            float a[8], bb[8];
            *(float4*)&a[0]  = *(float4*)&As[k][ty * 8];
            *(float4*)&a[4]  = *(float4*)&As[k][ty * 8 + 4];
            *(float4*)&bb[0] = *(float4*)&Bs[k][tx * 8];
            *(float4*)&bb[4] = *(float4*)&Bs[k][tx * 8 + 4];
            #pragma unroll
            for (int i = 0; i < 8; ++i)
                #pragma unroll
                for (int j = 0; j < 8; ++j)
                    acc[i][j] += a[i] * bb[j];
        }
        __syncthreads();
    }
    #pragma unroll
    for (int i = 0; i < 8; ++i) {
        int r = rbase + ty * 8 + i;             // channel within 256
        float bv = bias[r];
        #pragma unroll
        for (int j = 0; j < 8; ++j) acc[i][j] += bv;
        float* dst = C + ((size_t)b * CK + r) * NPIX + bxn + tx * 8;
        *(float4*)&dst[0] = *(float4*)&acc[i][0];
        *(float4*)&dst[4] = *(float4*)&acc[i][4];
    }
}

// ---------------- K2: BN batch stats over (b, n) per channel ----------------
__global__ void k2_stats(const float* __restrict__ fk_g, const float* __restrict__ fk_be,
                         const float* __restrict__ fq_g, const float* __restrict__ fq_be)
{
    int c = blockIdx.x;                         // 0..511
    const float* src = (c < CK) ? g_k1 : g_q2;
    int ch = c & (CK - 1);
    int tid = threadIdx.x;
    float s = 0.f, s2 = 0.f;
    for (int b = 0; b < BATCH; ++b) {
        const float* p = src + ((size_t)b * CK + ch) * NPIX;
        for (int n = tid; n < NPIX; n += 256) {
            float v = p[n];
            s += v; s2 += v * v;
        }
    }
    __shared__ float sh[256], sh2[256];
    sh[tid] = s; sh2[tid] = s2; __syncthreads();
    for (int o = 128; o; o >>= 1) {
        if (tid < o) { sh[tid] += sh[tid + o]; sh2[tid] += sh2[tid + o]; }
        __syncthreads();
    }
    if (tid == 0) {
        float M = (float)BATCH * NPIX;
        float mean = sh[0] / M;
        float var  = sh2[0] / M - mean * mean;
        float rstd = rsqrtf(var + EPSV);
        float g  = (c < CK) ? fk_g[ch]  : fq_g[ch];
        float be = (c < CK) ? fk_be[ch] : fq_be[ch];
        float a  = g * rstd;
        float bb = be - mean * a;
        if (c < CK) { g_aK[ch] = a; g_bK[ch] = bb; }
        else        { g_aQ[ch] = a; g_bQ[ch] = bb; }
    }
}

// ---------------- K3: proxy projections q1 / k2 (tiny; BN over P=19) ----------------
__global__ void k3_proxy(const float* __restrict__ pf,
                         const float* __restrict__ pq_w, const float* __restrict__ pq_b,
                         const float* __restrict__ pq_g, const float* __restrict__ pq_be,
                         const float* __restrict__ pk_w, const float* __restrict__ pk_b,
                         const float* __restrict__ pk_g, const float* __restrict__ pk_be)
{
    __shared__ float spf[CIN * NP];             // 38.9 KB
    int tid = threadIdx.x;
    for (int i = tid; i < CIN * NP; i += 256) spf[i] = pf[i];
    __syncthreads();
    const float *w, *bi, *g, *be; float* out;
    if (blockIdx.x == 0) { w = pq_w; bi = pq_b; g = pq_g; be = pq_be; out = g_q1; }
    else                 { w = pk_w; bi = pk_b; g = pk_g; be = pk_be; out = g_k2; }
    int k = tid;                                // one output channel per thread
    float acc[NP];
    float bv = bi[k];
    #pragma unroll
    for (int p = 0; p < NP; ++p) acc[p] = bv;
    for (int c = 0; c < CIN; ++c) {
        float wv = w[(size_t)k * CIN + c];
        #pragma unroll
        for (int p = 0; p < NP; ++p) acc[p] += wv * spf[c * NP + p];
    }
    float mean = 0.f;
    #pragma unroll
    for (int p = 0; p < NP; ++p) mean += acc[p];
    mean /= (float)NP;
    float var = 0.f;
    #pragma unroll
    for (int p = 0; p < NP; ++p) { float d = acc[p] - mean; var += d * d; }
    var /= (float)NP;
    float rstd = rsqrtf(var + EPSV);
    float gg = g[k], bb = be[k];
    #pragma unroll
    for (int p = 0; p < NP; ++p) {
        float z = (acc[p] - mean) * rstd * gg + bb;
        out[p * CK + k] = lrelu(z);
    }
}

// ---------------- K4: stage-1 logits  L1[b,p,n] = sum_k q1[p,k] * act(k1) ----------------
__global__ void k4_logits()
{
    __shared__ float q1s[NP * CK];
    __shared__ float aks[CK], bks[CK];
    int tid = threadIdx.x;                      // 128 threads
    for (int i = tid; i < NP * CK; i += 128) q1s[i] = g_q1[i];
    for (int i = tid; i < CK; i += 128) { aks[i] = g_aK[i]; bks[i] = g_bK[i]; }
    __syncthreads();
    int b = blockIdx.y;
    int n = blockIdx.x * 128 + tid;
    const float* kp = g_k1 + (size_t)b * CK * NPIX + n;
    float acc[NP] = {};
    for (int k = 0; k < CK; ++k) {
        float v = kp[(size_t)k * NPIX];
        v = lrelu(v * aks[k] + bks[k]);
        #pragma unroll
        for (int p = 0; p < NP; ++p) acc[p] += q1s[p * CK + k] * v;
    }
    float* Lp = g_L1 + (size_t)b * NP * NPIX + n;
    #pragma unroll
    for (int p = 0; p < NP; ++p) Lp[(size_t)p * NPIX] = acc[p];
}

// ---------------- K5: softmax row stats over N per (b,p) ----------------
__global__ void k5_smstats()
{
    int row = blockIdx.x;                       // 0..151
    const float* L = g_L1 + (size_t)row * NPIX;
    int tid = threadIdx.x;
    float m = -1e30f;
    for (int n = tid; n < NPIX; n += 256) m = fmaxf(m, L[n]);
    __shared__ float sm[256];
    sm[tid] = m; __syncthreads();
    for (int o = 128; o; o >>= 1) { if (tid < o) sm[tid] = fmaxf(sm[tid], sm[tid + o]); __syncthreads(); }
    float mx = sm[0];
    __syncthreads();
    float s = 0.f;
    for (int n = tid; n < NPIX; n += 256) s += expf(L[n] - mx);
    sm[tid] = s; __syncthreads();
    for (int o = 128; o; o >>= 1) { if (tid < o) sm[tid] += sm[tid + o]; __syncthreads(); }
    if (tid == 0) { g_rmax[row] = mx; g_rinv[row] = 1.f / sm[0]; }
}

// ---------------- K6a: t[b,c,p] += sum_n x[b,c,n] * sim1[b,p,n] ----------------
__global__ void k6a_t(const float* __restrict__ x)
{
    const int b  = blockIdx.y;
    const int n0 = blockIdx.x * 512;            // 32 chunks per batch
    __shared__ float xt[CIN * 17];              // 512 x 16 (+pad)
    __shared__ float ws[NP * 16];
    __shared__ float rmx[NP], rin[NP];
    int tid = threadIdx.x;                      // 256
    if (tid < NP) { rmx[tid] = g_rmax[b * NP + tid]; rin[tid] = g_rinv[b * NP + tid]; }
    float acc0[NP] = {}, acc1[NP] = {};
    const float* xb = x + (size_t)b * CIN * NPIX;
    const float* Lb = g_L1 + (size_t)b * NP * NPIX;
    const int c0 = tid, c1 = tid + 256;
    for (int t0 = 0; t0 < 512; t0 += 16) {
        int nb = n0 + t0;
        __syncthreads();
        for (int i = tid; i < CIN * 16; i += 256) {
            int c = i >> 4, nn = i & 15;
            xt[c * 17 + nn] = xb[(size_t)c * NPIX + nb + nn];
        }
        for (int i = tid; i < NP * 16; i += 256) {
            int p = i >> 4, nn = i & 15;
            ws[i] = expf(Lb[(size_t)p * NPIX + nb + nn] - rmx[p]) * rin[p];
        }
        __syncthreads();
        #pragma unroll
        for (int nn = 0; nn < 16; ++nn) {
            float x0 = xt[c0 * 17 + nn], x1 = xt[c1 * 17 + nn];
            #pragma unroll
            for (int p = 0; p < NP; ++p) {
                float w = ws[p * 16 + nn];
                acc0[p] += w * x0;
                acc1[p] += w * x1;
            }
        }
    }
    float* tb = g_t + (size_t)b * CIN * NP;
    #pragma unroll
    for (int p = 0; p < NP; ++p) {
        atomicAdd(&tb[(size_t)c0 * NP + p], acc0[p]);
        atomicAdd(&tb[(size_t)c1 * NP + p], acc1[p]);
    }
}

// ---------------- K6b: proxy_ctx[b,p,v] = fv_b[v] + sum_c fv_w[v,c] * t[b,c,p] ----------------
__global__ void k6b_pctx(const float* __restrict__ fv_w, const float* __restrict__ fv_b)
{
    int p = blockIdx.x, b = blockIdx.y;
    __shared__ float tc[CIN];
    int tid = threadIdx.x;                      // 256
    const float* tb = g_t + (size_t)b * CIN * NP + p;
    for (int i = tid; i < CIN; i += 256) tc[i] = tb[(size_t)i * NP];
    __syncthreads();
    int v = tid;
    float acc = fv_b[v];
    const float* w = fv_w + (size_t)v * CIN;
    for (int c = 0; c < CIN; ++c) acc += w[c] * tc[c];
    g_pctx[((size_t)b * NP + p) * CV + v] = acc;
}

// ---------------- K7pre: wpc[b,p,o] = sum_v W_w[o,v] * proxy_ctx[b,p,v] ----------------
__global__ void k7pre(const float* __restrict__ W_w)
{
    int p = blockIdx.x, b = blockIdx.y;
    __shared__ float pcs[CV];
    int tid = threadIdx.x;                      // 256
    pcs[tid] = g_pctx[((size_t)b * NP + p) * CV + tid];
    __syncthreads();
    for (int o = tid; o < COUT; o += 256) {
        const float* w = W_w + (size_t)o * CV;
        float acc = 0.f;
        for (int v = 0; v < CV; ++v) acc += w[v] * pcs[v];
        g_wpc[((size_t)b * NP + p) * COUT + o] = acc;
    }
}

// ---------------- K7a: stage-2 softmax per pixel (over P=19) ----------------
__global__ void k7a_sm2()
{
    __shared__ float k2s[NP * CK];
    __shared__ float aqs[CK], bqs[CK];
    int tid = threadIdx.x;                      // 128
    for (int i = tid; i < NP * CK; i += 128) k2s[i] = g_k2[i];
    for (int i = tid; i < CK; i += 128) { aqs[i] = g_aQ[i]; bqs[i] = g_bQ[i]; }
    __syncthreads();
    int b = blockIdx.y;
    int n = blockIdx.x * 128 + tid;
    const float* qp = g_q2 + (size_t)b * CK * NPIX + n;
    float lg[NP] = {};
    for (int k = 0; k < CK; ++k) {
        float v = qp[(size_t)k * NPIX];
        v = lrelu(v * aqs[k] + bqs[k]);
        #pragma unroll
        for (int p = 0; p < NP; ++p) lg[p] += k2s[p * CK + k] * v;
    }
    float mx = lg[0];
    #pragma unroll
    for (int p = 1; p < NP; ++p) mx = fmaxf(mx, lg[p]);
    float s = 0.f;
    #pragma unroll
    for (int p = 0; p < NP; ++p) { lg[p] = expf(lg[p] - mx); s += lg[p]; }
    float inv = 1.f / s;
    float* sp = g_sm2 + (size_t)b * NP * NPIX + n;
    #pragma unroll
    for (int p = 0; p < NP; ++p) sp[(size_t)p * NPIX] = lg[p] * inv;
}

// ---------------- K7b: out[b,o,n] = W_b[o] + sum_p sm2[b,n,p] * wpc[b,p,o] ----------------
__global__ void k7b_out(const float* __restrict__ W_b, float* __restrict__ out)
{
    __shared__ float wps[NP * COUT];            // 38.9 KB
    __shared__ float wbs[COUT];
    int tid = threadIdx.x;                      // 128
    int b = blockIdx.y;
    for (int i = tid; i < NP * COUT; i += 128) wps[i] = g_wpc[(size_t)b * NP * COUT + i];
    for (int i = tid; i < COUT; i += 128) wbs[i] = W_b[i];
    __syncthreads();
    int n = blockIdx.x * 128 + tid;
    float sm[NP];
    const float* sp = g_sm2 + (size_t)b * NP * NPIX + n;
    #pragma unroll
    for (int p = 0; p < NP; ++p) sm[p] = sp[(size_t)p * NPIX];
    float* op = out + (size_t)b * COUT * NPIX + n;
    for (int o = 0; o < COUT; ++o) {
        float acc = wbs[o];
        #pragma unroll
        for (int p = 0; p < NP; ++p) acc += sm[p] * wps[p * COUT + o];
        op[(size_t)o * NPIX] = acc;
    }
}

// ---------------- launch ----------------
extern "C" void kernel_launch(void* const* d_in, const int* in_sizes, int n_in,
                              void* d_out, int out_size)
{
    (void)in_sizes; (void)n_in; (void)out_size;
    const float* x     = (const float*)d_in[0];
    const float* pf    = (const float*)d_in[1];
    const float* fk_w  = (const float*)d_in[2];
    const float* fk_b  = (const float*)d_in[3];
    const float* fk_g  = (const float*)d_in[4];
    const float* fk_be = (const float*)d_in[5];
    const float* fq_w  = (const float*)d_in[6];
    const float* fq_b  = (const float*)d_in[7];
    const float* fq_g  = (const float*)d_in[8];
    const float* fq_be = (const float*)d_in[9];
    const float* fv_w  = (const float*)d_in[10];
    const float* fv_b  = (const float*)d_in[11];
    const float* pq_w  = (const float*)d_in[12];
    const float* pq_b  = (const float*)d_in[13];
    const float* pq_g  = (const float*)d_in[14];
    const float* pq_be = (const float*)d_in[15];
    const float* pk_w  = (const float*)d_in[16];
    const float* pk_b  = (const float*)d_in[17];
    const float* pk_g  = (const float*)d_in[18];
    const float* pk_be = (const float*)d_in[19];
    const float* W_w   = (const float*)d_in[20];
    const float* W_b   = (const float*)d_in[21];
    float* out = (float*)d_out;

    k0_zero<<<(BATCH * CIN * NP + 255) / 256, 256>>>();
    k1_proj<<<dim3(NPIX / 128, 4, BATCH), 256>>>(x, fk_w, fk_b, fq_w, fq_b);
    k2_stats<<<2 * CK, 256>>>(fk_g, fk_be, fq_g, fq_be);
    k3_proxy<<<2, 256>>>(pf, pq_w, pq_b, pq_g, pq_be, pk_w, pk_b, pk_g, pk_be);
    k4_logits<<<dim3(NPIX / 128, BATCH), 128>>>();
    k5_smstats<<<BATCH * NP, 256>>>();
    k6a_t<<<dim3(NPIX / 512, BATCH), 256>>>(x);
    k6b_pctx<<<dim3(NP, BATCH), 256>>>(fv_w, fv_b);
    k7pre<<<dim3(NP, BATCH), 256>>>(W_w);
    k7a_sm2<<<dim3(NPIX / 128, BATCH), 128>>>();
    k7b_out<<<dim3(NPIX / 128, BATCH), 128>>>(W_b, out);
}